// round 2
// baseline (speedup 1.0000x reference)
#include <cuda_runtime.h>
#include <math.h>
#include <stdint.h>

// Problem constants
#define NN    20000
#define EE    160000
#define IND   128
#define HIDD  96
#define NH    6
#define NG    512
#define NCLS  128
#define HD    576          // NH * HIDD
#define QC    1824         // packed cols: q(576) k(576) v(576) skip(96)

// ---------------- scratch (allocation-free) ----------------
__device__ float g_qkvs[(size_t)NN * QC];       // ~146 MB
__device__ float g_h[NN * HIDD];
__device__ float g_hsum[NN * HIDD];
__device__ float g_Wcat[IND * QC];
__device__ float g_bcat[QC];
__device__ int   g_src[EE], g_dst[EE], g_srcs[EE];
__device__ int   g_deg[NN], g_rowptr[NN + 1], g_cursor[NN];
__device__ int   g_batch[NN];
__device__ float g_pool[NG * HIDD];
__device__ int   g_cnt[NG];
__device__ float g_gbuf[NG * HIDD];
__device__ float g_wn[NCLS * HIDD];
__device__ int   g_is64;

// ---------------- dtype detection (int32 vs int64 indices) ----------------
__global__ void detect_kernel(const unsigned* w) {
    __shared__ int any;
    if (threadIdx.x == 0) any = 0;
    __syncthreads();
    // int64 layout: every odd 32-bit word is the zero high half (indices < 2^31).
    // int32 layout: odd words are random indices in [0,20000) -> some nonzero.
    for (int i = threadIdx.x; i < 2048; i += blockDim.x)
        if (w[2 * i + 1] != 0u) any = 1;
    __syncthreads();
    if (threadIdx.x == 0) g_is64 = (any == 0);
}

__global__ void extract_edges(const void* ei) {
    int e = blockIdx.x * blockDim.x + threadIdx.x;
    if (e >= EE) return;
    if (g_is64) {
        const long long* p = (const long long*)ei;
        g_src[e] = (int)p[e];
        g_dst[e] = (int)p[EE + e];
    } else {
        const int* p = (const int*)ei;
        g_src[e] = p[e];
        g_dst[e] = p[EE + e];
    }
}

__global__ void extract_batch(const void* bt) {
    int n = blockIdx.x * blockDim.x + threadIdx.x;
    if (n >= NN) return;
    g_batch[n] = g_is64 ? (int)((const long long*)bt)[n] : ((const int*)bt)[n];
}

// ---------------- CSR build (dst-sorted edges) ----------------
__global__ void zero_deg_kernel() {
    int i = blockIdx.x * blockDim.x + threadIdx.x;
    if (i < NN) g_deg[i] = 0;
}

__global__ void deg_kernel() {
    int e = blockIdx.x * blockDim.x + threadIdx.x;
    if (e < EE) atomicAdd(&g_deg[g_dst[e]], 1);
}

__global__ void scan_kernel() {   // one block, 512 threads
    __shared__ int part[512];
    const int T = 512;
    const int per = (NN + T - 1) / T;    // 40
    int tid = threadIdx.x;
    int base = tid * per;
    int sum = 0;
    for (int i = 0; i < per; i++) {
        int idx = base + i;
        if (idx < NN) sum += g_deg[idx];
    }
    part[tid] = sum;
    __syncthreads();
    for (int off = 1; off < T; off <<= 1) {
        int v = (tid >= off) ? part[tid - off] : 0;
        __syncthreads();
        part[tid] += v;
        __syncthreads();
    }
    int run = tid ? part[tid - 1] : 0;
    for (int i = 0; i < per; i++) {
        int idx = base + i;
        if (idx < NN) {
            g_rowptr[idx] = run;
            g_cursor[idx] = run;
            run += g_deg[idx];
        }
    }
    if (tid == T - 1) g_rowptr[NN] = part[T - 1];
}

__global__ void scatter_kernel() {
    int e = blockIdx.x * blockDim.x + threadIdx.x;
    if (e >= EE) return;
    int d = g_dst[e];
    int pos = atomicAdd(&g_cursor[d], 1);
    g_srcs[pos] = g_src[e];
}

// ---------------- per-layer weight packing ----------------
__global__ void pack_kernel(const float* __restrict__ Wq, const float* __restrict__ Wk,
                            const float* __restrict__ Wv, const float* __restrict__ Ws,
                            const float* __restrict__ bq, const float* __restrict__ bk,
                            const float* __restrict__ bv, const float* __restrict__ bs,
                            int K) {
    int idx = blockIdx.x * blockDim.x + threadIdx.x;
    if (idx < QC) {
        int j = idx;
        g_bcat[j] = (j < 576) ? bq[j] : (j < 1152) ? bk[j - 576]
                  : (j < 1728) ? bv[j - 1152] : bs[j - 1728];
    }
    if (idx >= K * QC) return;
    int kk = idx / QC, j = idx - kk * QC;
    float v = (j < 576)  ? Wq[kk * 576 + j]
            : (j < 1152) ? Wk[kk * 576 + (j - 576)]
            : (j < 1728) ? Wv[kk * 576 + (j - 1152)]
                         : Ws[kk * 96 + (j - 1728)];
    g_Wcat[idx] = v;
}

// ---------------- fused QKV+skip SGEMM:  C[NN,1824] = A[NN,K] * Wcat + bcat ----------------
// BM=128, BN=96, BK=16, 256 threads, TM=8 x TN=6
__global__ void __launch_bounds__(256) gemm_kernel(const float* __restrict__ X, int useX, int K) {
    const float* __restrict__ A = useX ? X : g_h;
    __shared__ float As[16][132];   // padded: avoid STS bank conflicts
    __shared__ float Bs[16][96];
    int tid = threadIdx.x;
    int m0 = blockIdx.y * 128, n0 = blockIdx.x * 96;
    int tx = tid & 15, ty = tid >> 4;

    float acc[8][6];
#pragma unroll
    for (int i = 0; i < 8; i++)
#pragma unroll
        for (int j = 0; j < 6; j++) acc[i][j] = 0.f;

    for (int k0 = 0; k0 < K; k0 += 16) {
        int mrow = tid >> 2, kq = (tid & 3) * 4;
#pragma unroll
        for (int hh = 0; hh < 2; hh++) {
            int m = mrow + hh * 64;
            int gm = m0 + m;
            float4 v = make_float4(0.f, 0.f, 0.f, 0.f);
            if (gm < NN) v = *(const float4*)(A + (size_t)gm * K + k0 + kq);
            As[kq + 0][m] = v.x;
            As[kq + 1][m] = v.y;
            As[kq + 2][m] = v.z;
            As[kq + 3][m] = v.w;
        }
#pragma unroll
        for (int i = 0; i < 6; i++) {
            int idx = tid + i * 256;          // 0..1535
            int kk = idx / 96, col = idx - kk * 96;
            Bs[kk][col] = g_Wcat[(size_t)(k0 + kk) * QC + n0 + col];
        }
        __syncthreads();
#pragma unroll
        for (int kk = 0; kk < 16; kk++) {
            float a[8], b[6];
#pragma unroll
            for (int i = 0; i < 8; i++) a[i] = As[kk][ty * 8 + i];
#pragma unroll
            for (int j = 0; j < 6; j++) b[j] = Bs[kk][tx * 6 + j];
#pragma unroll
            for (int i = 0; i < 8; i++)
#pragma unroll
                for (int j = 0; j < 6; j++) acc[i][j] += a[i] * b[j];
        }
        __syncthreads();
    }
#pragma unroll
    for (int i = 0; i < 8; i++) {
        int gm = m0 + ty * 8 + i;
        if (gm >= NN) continue;
#pragma unroll
        for (int j = 0; j < 6; j++) {
            int col = n0 + tx * 6 + j;
            g_qkvs[(size_t)gm * QC + col] = acc[i][j] + g_bcat[col];
        }
    }
}

// ---------------- attention: one warp per (node, head), online softmax over CSR ----------------
__global__ void zero_hsum_kernel() {
    int i = blockIdx.x * blockDim.x + threadIdx.x;
    if (i < NN * HIDD) g_hsum[i] = 0.f;
}

__global__ void attn_kernel() {
    int gw = (blockIdx.x * blockDim.x + threadIdx.x) >> 5;
    int lane = threadIdx.x & 31;
    if (gw >= NN * NH) return;
    int n = gw / NH, h = gw - n * NH;
    const float* qr = g_qkvs + (size_t)n * QC + h * HIDD;
    float q0 = qr[lane], q1 = qr[lane + 32], q2 = qr[lane + 64];
    int beg = g_rowptr[n], end = g_rowptr[n + 1];
    float m = -INFINITY, s = 0.f, a0 = 0.f, a1 = 0.f, a2 = 0.f;
    for (int i = beg; i < end; i++) {
        int sv = g_srcs[i];
        const float* kr = g_qkvs + (size_t)sv * QC + 576 + h * HIDD;
        float p = q0 * kr[lane] + q1 * kr[lane + 32] + q2 * kr[lane + 64];
        p += __shfl_xor_sync(0xffffffffu, p, 16);
        p += __shfl_xor_sync(0xffffffffu, p, 8);
        p += __shfl_xor_sync(0xffffffffu, p, 4);
        p += __shfl_xor_sync(0xffffffffu, p, 2);
        p += __shfl_xor_sync(0xffffffffu, p, 1);
        float alpha = p * 0.10206207261596577f;   // 1/sqrt(96)
        float mn = fmaxf(m, alpha);
        float corr = expf(m - mn);                // exp(-inf)=0 on first edge
        float w = expf(alpha - mn);
        const float* vr = kr + 576;
        a0 = a0 * corr + w * vr[lane];
        a1 = a1 * corr + w * vr[lane + 32];
        a2 = a2 * corr + w * vr[lane + 64];
        s = s * corr + w;
        m = mn;
    }
    if (s > 0.f) {
        float inv = 1.f / (6.f * s);              // head mean folded in
        float* hs = g_hsum + n * HIDD;
        atomicAdd(hs + lane, a0 * inv);
        atomicAdd(hs + lane + 32, a1 * inv);
        atomicAdd(hs + lane + 64, a2 * inv);
    }
}

__global__ void combine_kernel() {
    int i = blockIdx.x * blockDim.x + threadIdx.x;
    if (i >= NN * HIDD) return;
    int n = i / HIDD, d = i - n * HIDD;
    float v = g_hsum[i] + g_qkvs[(size_t)n * QC + 1728 + d];   // skip (bias included)
    g_h[i] = fmaxf(v, 0.f);
}

// ---------------- pooling + head ----------------
__global__ void zero_pool_kernel() {
    int i = blockIdx.x * blockDim.x + threadIdx.x;
    if (i < NG * HIDD) g_pool[i] = 0.f;
    if (i < NG) g_cnt[i] = 0;
}

__global__ void pool_kernel() {
    int i = blockIdx.x * blockDim.x + threadIdx.x;
    if (i >= NN * HIDD) return;
    int n = i / HIDD, d = i - n * HIDD;
    atomicAdd(&g_pool[g_batch[n] * HIDD + d], g_h[i]);
}

__global__ void cnt_kernel() {
    int n = blockIdx.x * blockDim.x + threadIdx.x;
    if (n < NN) atomicAdd(&g_cnt[g_batch[n]], 1);
}

__global__ void head_kernel(const float* __restrict__ fc1w, const float* __restrict__ fc1b,
                            const float* __restrict__ fc2w, const float* __restrict__ fc2b) {
    int b = blockIdx.x, d = threadIdx.x;   // 512 blocks x 96 threads
    __shared__ float sg[96], st[96];
    __shared__ float snorm;
    float c = fmaxf((float)g_cnt[b], 1.f);
    sg[d] = g_pool[b * HIDD + d] / c;
    __syncthreads();
    float acc = fc1b[d];
    for (int i = 0; i < HIDD; i++) acc += sg[i] * fc1w[i * HIDD + d];
    st[d] = fmaxf(acc, 0.f);
    __syncthreads();
    acc = fc2b[d];
    for (int i = 0; i < HIDD; i++) acc += st[i] * fc2w[i * HIDD + d];
    float o = fmaxf(acc, 0.f);
    sg[d] = o * o;
    __syncthreads();
    if (d == 0) {
        float ss = 0.f;
        for (int i = 0; i < HIDD; i++) ss += sg[i];
        snorm = sqrtf(ss) + 1e-12f;
    }
    __syncthreads();
    g_gbuf[b * HIDD + d] = o / snorm;
}

__global__ void wn_kernel(const float* __restrict__ arcw) {
    int cIdx = blockIdx.x, d = threadIdx.x;   // 128 blocks x 96 threads
    __shared__ float sq[96];
    __shared__ float sn;
    float w = arcw[cIdx * HIDD + d];
    sq[d] = w * w;
    __syncthreads();
    if (d == 0) {
        float ss = 0.f;
        for (int i = 0; i < HIDD; i++) ss += sq[i];
        sn = sqrtf(ss) + 1e-12f;
    }
    __syncthreads();
    g_wn[cIdx * HIDD + d] = w / sn;
}

__global__ void out_kernel(float* __restrict__ out) {
    int t = blockIdx.x * blockDim.x + threadIdx.x;
    if (t >= NG * NCLS) return;
    int g = t / NCLS, c = t - g * NCLS;
    float acc = 0.f;
    for (int d = 0; d < HIDD; d++) acc += g_gbuf[g * HIDD + d] * g_wn[c * HIDD + d];
    out[t] = 30.f * acc;
}

// ---------------- driver ----------------
extern "C" void kernel_launch(void* const* d_in, const int* in_sizes, int n_in,
                              void* d_out, int out_size) {
    const float* x    = (const float*)d_in[0];
    const void*  ei   = d_in[1];
    const void*  bt   = d_in[2];
    const float* Wq1  = (const float*)d_in[3];
    const float* bq1  = (const float*)d_in[4];
    const float* Wk1  = (const float*)d_in[5];
    const float* bk1  = (const float*)d_in[6];
    const float* Wv1  = (const float*)d_in[7];
    const float* bv1  = (const float*)d_in[8];
    const float* Ws1  = (const float*)d_in[9];
    const float* bs1  = (const float*)d_in[10];
    const float* Wq_r = (const float*)d_in[11];   // [4,96,576]
    const float* bq_r = (const float*)d_in[12];   // [4,576]
    const float* Wk_r = (const float*)d_in[13];
    const float* bk_r = (const float*)d_in[14];
    const float* Wv_r = (const float*)d_in[15];
    const float* bv_r = (const float*)d_in[16];
    const float* Ws_r = (const float*)d_in[17];   // [4,96,96]
    const float* bs_r = (const float*)d_in[18];   // [4,96]
    const float* fc1w = (const float*)d_in[19];
    const float* fc1b = (const float*)d_in[20];
    const float* fc2w = (const float*)d_in[21];
    const float* fc2b = (const float*)d_in[22];
    const float* arcw = (const float*)d_in[23];
    float* out = (float*)d_out;

    // index normalization + CSR build
    detect_kernel<<<1, 256>>>((const unsigned*)ei);
    extract_edges<<<(EE + 255) / 256, 256>>>(ei);
    extract_batch<<<(NN + 255) / 256, 256>>>(bt);
    zero_deg_kernel<<<(NN + 255) / 256, 256>>>();
    deg_kernel<<<(EE + 255) / 256, 256>>>();
    scan_kernel<<<1, 512>>>();
    scatter_kernel<<<(EE + 255) / 256, 256>>>();

    dim3 ggrid(QC / 96, (NN + 127) / 128);   // 19 x 157
    for (int l = 0; l < 5; l++) {
        if (l == 0) {
            pack_kernel<<<(IND * QC + 255) / 256, 256>>>(Wq1, Wk1, Wv1, Ws1, bq1, bk1, bv1, bs1, IND);
        } else {
            int i = l - 1;
            pack_kernel<<<(HIDD * QC + 255) / 256, 256>>>(
                Wq_r + (size_t)i * HIDD * HD, Wk_r + (size_t)i * HIDD * HD,
                Wv_r + (size_t)i * HIDD * HD, Ws_r + (size_t)i * HIDD * HIDD,
                bq_r + (size_t)i * HD, bk_r + (size_t)i * HD,
                bv_r + (size_t)i * HD, bs_r + (size_t)i * HIDD, HIDD);
        }
        zero_hsum_kernel<<<(NN * HIDD + 255) / 256, 256>>>();
        gemm_kernel<<<ggrid, 256>>>(x, l == 0 ? 1 : 0, l == 0 ? IND : HIDD);
        attn_kernel<<<(NN * NH + 7) / 8, 256>>>();
        combine_kernel<<<(NN * HIDD + 255) / 256, 256>>>();
    }

    zero_pool_kernel<<<(NG * HIDD + 255) / 256, 256>>>();
    pool_kernel<<<(NN * HIDD + 255) / 256, 256>>>();
    cnt_kernel<<<(NN + 255) / 256, 256>>>();
    head_kernel<<<NG, HIDD>>>(fc1w, fc1b, fc2w, fc2b);
    wn_kernel<<<NCLS, HIDD>>>(arcw);
    out_kernel<<<(NG * NCLS + 255) / 256, 256>>>(out);
}

// round 3
// speedup vs baseline: 1.7350x; 1.7350x over previous
#include <cuda_runtime.h>
#include <math.h>
#include <stdint.h>

// Problem constants
#define NN    20000
#define EE    160000
#define IND   128
#define HIDD  96
#define NH    6
#define NG    512
#define NCLS  128
#define HD    576          // NH * HIDD
#define QC    1824         // packed cols: q(576) k(576) v(576) skip(96)

// GEMM tiling
#define BM 128
#define BN 96
#define BK 32

// ---------------- scratch (allocation-free) ----------------
__device__ float g_qkvs[(size_t)NN * QC];       // ~146 MB
__device__ float g_h[NN * HIDD];
__device__ float g_Wcat[IND * QC];
__device__ float g_bcat[QC];
__device__ int   g_src[EE], g_dst[EE], g_srcs[EE];
__device__ int   g_deg[NN], g_rowptr[NN + 1], g_cursor[NN];
__device__ int   g_batch[NN];
__device__ float g_pool[NG * HIDD];
__device__ int   g_cnt[NG];
__device__ float g_gbuf[NG * HIDD];
__device__ float g_wn[NCLS * HIDD];
__device__ int   g_is64;

// ---------------- helpers ----------------
__device__ __forceinline__ float f2t(float x) {
    unsigned r;
    asm("cvt.rna.tf32.f32 %0, %1;" : "=r"(r) : "f"(x));
    return __uint_as_float(r);
}

__device__ __forceinline__ void mma8(float* c, const unsigned* a, const unsigned* b) {
    asm volatile(
        "mma.sync.aligned.m16n8k8.row.col.f32.tf32.tf32.f32 "
        "{%0,%1,%2,%3}, {%4,%5,%6,%7}, {%8,%9}, {%0,%1,%2,%3};"
        : "+f"(c[0]), "+f"(c[1]), "+f"(c[2]), "+f"(c[3])
        : "r"(a[0]), "r"(a[1]), "r"(a[2]), "r"(a[3]), "r"(b[0]), "r"(b[1]));
}

// ---------------- dtype detection (int32 vs int64 indices) ----------------
__global__ void detect_kernel(const unsigned* w) {
    __shared__ int any;
    if (threadIdx.x == 0) any = 0;
    __syncthreads();
    for (int i = threadIdx.x; i < 2048; i += blockDim.x)
        if (w[2 * i + 1] != 0u) any = 1;
    __syncthreads();
    if (threadIdx.x == 0) g_is64 = (any == 0);
}

// edges + batch + zero deg, one kernel
__global__ void extract_all(const void* ei, const void* bt) {
    int e = blockIdx.x * blockDim.x + threadIdx.x;
    if (e < EE) {
        if (g_is64) {
            const long long* p = (const long long*)ei;
            g_src[e] = (int)p[e];
            g_dst[e] = (int)p[EE + e];
        } else {
            const int* p = (const int*)ei;
            g_src[e] = p[e];
            g_dst[e] = p[EE + e];
        }
    }
    if (e < NN) {
        g_deg[e] = 0;
        g_batch[e] = g_is64 ? (int)((const long long*)bt)[e] : ((const int*)bt)[e];
    }
}

__global__ void deg_kernel() {
    int e = blockIdx.x * blockDim.x + threadIdx.x;
    if (e < EE) atomicAdd(&g_deg[g_dst[e]], 1);
}

__global__ void scan_kernel() {   // one block, 512 threads
    __shared__ int part[512];
    const int T = 512;
    const int per = (NN + T - 1) / T;
    int tid = threadIdx.x;
    int base = tid * per;
    int sum = 0;
    for (int i = 0; i < per; i++) {
        int idx = base + i;
        if (idx < NN) sum += g_deg[idx];
    }
    part[tid] = sum;
    __syncthreads();
    for (int off = 1; off < T; off <<= 1) {
        int v = (tid >= off) ? part[tid - off] : 0;
        __syncthreads();
        part[tid] += v;
        __syncthreads();
    }
    int run = tid ? part[tid - 1] : 0;
    for (int i = 0; i < per; i++) {
        int idx = base + i;
        if (idx < NN) {
            g_rowptr[idx] = run;
            g_cursor[idx] = run;
            run += g_deg[idx];
        }
    }
    if (tid == T - 1) g_rowptr[NN] = part[T - 1];
}

// ---------------- weight packing ----------------
__device__ __forceinline__ void pack_one(int idx,
    const float* Wq, const float* Wk, const float* Wv, const float* Ws,
    const float* bq, const float* bk, const float* bv, const float* bs, int K) {
    if (idx < QC) {
        int j = idx;
        g_bcat[j] = (j < 576) ? bq[j] : (j < 1152) ? bk[j - 576]
                  : (j < 1728) ? bv[j - 1152] : bs[j - 1728];
    }
    if (idx >= K * QC) return;
    int kk = idx / QC, j = idx - kk * QC;
    float v = (j < 576)  ? Wq[kk * 576 + j]
            : (j < 1152) ? Wk[kk * 576 + (j - 576)]
            : (j < 1728) ? Wv[kk * 576 + (j - 1152)]
                         : Ws[kk * 96 + (j - 1728)];
    g_Wcat[idx] = v;
}

// scatter CSR + pack layer-0 weights (grid sized to cover IND*QC)
__global__ void scatter_pack0(const float* __restrict__ Wq, const float* __restrict__ Wk,
                              const float* __restrict__ Wv, const float* __restrict__ Ws,
                              const float* __restrict__ bq, const float* __restrict__ bk,
                              const float* __restrict__ bv, const float* __restrict__ bs) {
    int i = blockIdx.x * blockDim.x + threadIdx.x;
    if (i < EE) {
        int d = g_dst[i];
        int pos = atomicAdd(&g_cursor[d], 1);
        g_srcs[pos] = g_src[i];
    }
    pack_one(i, Wq, Wk, Wv, Ws, bq, bk, bv, bs, IND);
}

__global__ void pack_kernel(const float* __restrict__ Wq, const float* __restrict__ Wk,
                            const float* __restrict__ Wv, const float* __restrict__ Ws,
                            const float* __restrict__ bq, const float* __restrict__ bk,
                            const float* __restrict__ bv, const float* __restrict__ bs,
                            int K) {
    int idx = blockIdx.x * blockDim.x + threadIdx.x;
    pack_one(idx, Wq, Wk, Wv, Ws, bq, bk, bv, bs, K);
}

// ---------------- TF32 tensor-core GEMM:  C[NN,1824] = A[NN,K] * Wcat + bcat ----------------
// BM=128, BN=96, BK=32; 256 threads = 8 warps (4 x 2), warp tile 32x48.
__global__ void __launch_bounds__(256) gemm_tc(const float* __restrict__ X, int useX, int K) {
    const float* __restrict__ A = useX ? X : g_h;
    __shared__ __align__(16) float As[BM][BK + 4];   // [m][k], pad 4 -> row 144B
    __shared__ __align__(16) float Bs[BK][BN + 8];   // [k][n], pad 8 -> row 416B
    int tid = threadIdx.x;
    int m0 = blockIdx.y * BM, n0 = blockIdx.x * BN;
    int wid = tid >> 5, lane = tid & 31;
    int wm = wid & 3, wn = wid >> 2;       // warp grid 4 x 2
    int g = lane >> 2, t = lane & 3;

    float acc[2][6][4];
#pragma unroll
    for (int i = 0; i < 2; i++)
#pragma unroll
        for (int j = 0; j < 6; j++)
#pragma unroll
            for (int q = 0; q < 4; q++) acc[i][j][q] = 0.f;

    int c4 = tid & 7, rbase = tid >> 3;    // A: 8 float4 per row of 32 floats

    for (int k0 = 0; k0 < K; k0 += BK) {
        // load A tile 128x32 (4 float4 per thread)
#pragma unroll
        for (int i = 0; i < 4; i++) {
            int m = rbase + i * 32;
            int gm = m0 + m;
            float4 v = make_float4(0.f, 0.f, 0.f, 0.f);
            if (gm < NN) v = *(const float4*)(A + (size_t)gm * K + k0 + c4 * 4);
            float4 w = make_float4(f2t(v.x), f2t(v.y), f2t(v.z), f2t(v.w));
            *(float4*)&As[m][c4 * 4] = w;
        }
        // load B tile 32x96 (3 float4 per thread)
#pragma unroll
        for (int i = 0; i < 3; i++) {
            int idx = tid + i * 256;
            int kk = idx / 24, cc = idx - kk * 24;
            float4 v = *(const float4*)(g_Wcat + (size_t)(k0 + kk) * QC + n0 + cc * 4);
            float4 w = make_float4(f2t(v.x), f2t(v.y), f2t(v.z), f2t(v.w));
            *(float4*)&Bs[kk][cc * 4] = w;
        }
        __syncthreads();
#pragma unroll
        for (int ks = 0; ks < BK; ks += 8) {
            unsigned af[2][4], bf[6][2];
#pragma unroll
            for (int mt = 0; mt < 2; mt++) {
                int mm = wm * 32 + mt * 16 + g;
                af[mt][0] = __float_as_uint(As[mm][ks + t]);
                af[mt][1] = __float_as_uint(As[mm + 8][ks + t]);
                af[mt][2] = __float_as_uint(As[mm][ks + t + 4]);
                af[mt][3] = __float_as_uint(As[mm + 8][ks + t + 4]);
            }
#pragma unroll
            for (int nt = 0; nt < 6; nt++) {
                int nn2 = wn * 48 + nt * 8 + g;
                bf[nt][0] = __float_as_uint(Bs[ks + t][nn2]);
                bf[nt][1] = __float_as_uint(Bs[ks + t + 4][nn2]);
            }
#pragma unroll
            for (int mt = 0; mt < 2; mt++)
#pragma unroll
                for (int nt = 0; nt < 6; nt++)
                    mma8(acc[mt][nt], af[mt], bf[nt]);
        }
        __syncthreads();
    }
    // epilogue: add bias, write float2 pairs
#pragma unroll
    for (int mt = 0; mt < 2; mt++) {
        int r0 = m0 + wm * 32 + mt * 16 + g;
#pragma unroll
        for (int nt = 0; nt < 6; nt++) {
            int col = n0 + wn * 48 + nt * 8 + 2 * t;
            float b0 = g_bcat[col], b1 = g_bcat[col + 1];
            if (r0 < NN) {
                float2 v = make_float2(acc[mt][nt][0] + b0, acc[mt][nt][1] + b1);
                *(float2*)(g_qkvs + (size_t)r0 * QC + col) = v;
            }
            int r1 = r0 + 8;
            if (r1 < NN) {
                float2 v = make_float2(acc[mt][nt][2] + b0, acc[mt][nt][3] + b1);
                *(float2*)(g_qkvs + (size_t)r1 * QC + col) = v;
            }
        }
    }
}

// ---------------- fused attention: one block (6 warps = 6 heads) per node ----------------
__global__ void __launch_bounds__(192) attn_fused() {
    __shared__ float red[NH][HIDD];
    int n = blockIdx.x;
    int wid = threadIdx.x >> 5, lane = threadIdx.x & 31;
    const float* qr = g_qkvs + (size_t)n * QC + wid * HIDD;
    float q0 = qr[lane], q1 = qr[lane + 32], q2 = qr[lane + 64];
    int beg = g_rowptr[n], end = g_rowptr[n + 1];
    float m = -INFINITY, s = 0.f, a0 = 0.f, a1 = 0.f, a2 = 0.f;
    for (int i = beg; i < end; i++) {
        int sv = __ldg(&g_srcs[i]);
        const float* kr = g_qkvs + (size_t)sv * QC + 576 + wid * HIDD;
        float p = q0 * kr[lane] + q1 * kr[lane + 32] + q2 * kr[lane + 64];
        p += __shfl_xor_sync(0xffffffffu, p, 16);
        p += __shfl_xor_sync(0xffffffffu, p, 8);
        p += __shfl_xor_sync(0xffffffffu, p, 4);
        p += __shfl_xor_sync(0xffffffffu, p, 2);
        p += __shfl_xor_sync(0xffffffffu, p, 1);
        float alpha = p * 0.10206207261596577f;   // 1/sqrt(96)
        float mn = fmaxf(m, alpha);
        float corr = expf(m - mn);
        float w = expf(alpha - mn);
        const float* vr = kr + 576;
        a0 = a0 * corr + w * vr[lane];
        a1 = a1 * corr + w * vr[lane + 32];
        a2 = a2 * corr + w * vr[lane + 64];
        s = s * corr + w;
        m = mn;
    }
    float inv = (s > 0.f) ? 1.f / (6.f * s) : 0.f;   // head mean folded in
    red[wid][lane] = a0 * inv;
    red[wid][lane + 32] = a1 * inv;
    red[wid][lane + 64] = a2 * inv;
    __syncthreads();
    if (threadIdx.x < HIDD) {
        int d = threadIdx.x;
        float v = red[0][d] + red[1][d] + red[2][d] + red[3][d] + red[4][d] + red[5][d];
        v += g_qkvs[(size_t)n * QC + 1728 + d];   // skip (bias included)
        g_h[n * HIDD + d] = fmaxf(v, 0.f);
    }
}

// ---------------- pooling + head ----------------
__global__ void zero_pool_kernel() {
    int i = blockIdx.x * blockDim.x + threadIdx.x;
    if (i < NG * HIDD) g_pool[i] = 0.f;
    if (i < NG) g_cnt[i] = 0;
}

__global__ void pool_kernel() {
    int i = blockIdx.x * blockDim.x + threadIdx.x;
    if (i >= NN * HIDD) return;
    int n = i / HIDD, d = i - n * HIDD;
    atomicAdd(&g_pool[g_batch[n] * HIDD + d], g_h[i]);
    if (d == 0) atomicAdd(&g_cnt[g_batch[n]], 1);
}

__global__ void head_kernel(const float* __restrict__ fc1w, const float* __restrict__ fc1b,
                            const float* __restrict__ fc2w, const float* __restrict__ fc2b) {
    int b = blockIdx.x, d = threadIdx.x;
    __shared__ float sg[96], st[96];
    __shared__ float snorm;
    float c = fmaxf((float)g_cnt[b], 1.f);
    sg[d] = g_pool[b * HIDD + d] / c;
    __syncthreads();
    float acc = fc1b[d];
    for (int i = 0; i < HIDD; i++) acc += sg[i] * fc1w[i * HIDD + d];
    st[d] = fmaxf(acc, 0.f);
    __syncthreads();
    acc = fc2b[d];
    for (int i = 0; i < HIDD; i++) acc += st[i] * fc2w[i * HIDD + d];
    float o = fmaxf(acc, 0.f);
    sg[d] = o * o;
    __syncthreads();
    if (d == 0) {
        float ss = 0.f;
        for (int i = 0; i < HIDD; i++) ss += sg[i];
        snorm = sqrtf(ss) + 1e-12f;
    }
    __syncthreads();
    g_gbuf[b * HIDD + d] = o / snorm;
}

__global__ void wn_kernel(const float* __restrict__ arcw) {
    int cIdx = blockIdx.x, d = threadIdx.x;
    __shared__ float sq[96];
    __shared__ float sn;
    float w = arcw[cIdx * HIDD + d];
    sq[d] = w * w;
    __syncthreads();
    if (d == 0) {
        float ss = 0.f;
        for (int i = 0; i < HIDD; i++) ss += sq[i];
        sn = sqrtf(ss) + 1e-12f;
    }
    __syncthreads();
    g_wn[cIdx * HIDD + d] = w / sn;
}

__global__ void out_kernel(float* __restrict__ out) {
    int t = blockIdx.x * blockDim.x + threadIdx.x;
    if (t >= NG * NCLS) return;
    int g = t / NCLS, c = t - g * NCLS;
    float acc = 0.f;
    for (int d = 0; d < HIDD; d++) acc += g_gbuf[g * HIDD + d] * g_wn[c * HIDD + d];
    out[t] = 30.f * acc;
}

// ---------------- driver ----------------
extern "C" void kernel_launch(void* const* d_in, const int* in_sizes, int n_in,
                              void* d_out, int out_size) {
    const float* x    = (const float*)d_in[0];
    const void*  ei   = d_in[1];
    const void*  bt   = d_in[2];
    const float* Wq1  = (const float*)d_in[3];
    const float* bq1  = (const float*)d_in[4];
    const float* Wk1  = (const float*)d_in[5];
    const float* bk1  = (const float*)d_in[6];
    const float* Wv1  = (const float*)d_in[7];
    const float* bv1  = (const float*)d_in[8];
    const float* Ws1  = (const float*)d_in[9];
    const float* bs1  = (const float*)d_in[10];
    const float* Wq_r = (const float*)d_in[11];
    const float* bq_r = (const float*)d_in[12];
    const float* Wk_r = (const float*)d_in[13];
    const float* bk_r = (const float*)d_in[14];
    const float* Wv_r = (const float*)d_in[15];
    const float* bv_r = (const float*)d_in[16];
    const float* Ws_r = (const float*)d_in[17];
    const float* bs_r = (const float*)d_in[18];
    const float* fc1w = (const float*)d_in[19];
    const float* fc1b = (const float*)d_in[20];
    const float* fc2w = (const float*)d_in[21];
    const float* fc2b = (const float*)d_in[22];
    const float* arcw = (const float*)d_in[23];
    float* out = (float*)d_out;

    // launches 0..4: preprocessing (so launch #5 = gemm layer 0 is ncu-profiled)
    detect_kernel<<<1, 256>>>((const unsigned*)ei);
    extract_all<<<(EE + 255) / 256, 256>>>(ei, bt);
    deg_kernel<<<(EE + 255) / 256, 256>>>();
    scan_kernel<<<1, 512>>>();
    scatter_pack0<<<(IND * QC + 255) / 256, 256>>>(Wq1, Wk1, Wv1, Ws1, bq1, bk1, bv1, bs1);

    dim3 ggrid(QC / BN, (NN + BM - 1) / BM);   // 19 x 157
    for (int l = 0; l < 5; l++) {
        if (l > 0) {
            int i = l - 1;
            pack_kernel<<<(HIDD * QC + 255) / 256, 256>>>(
                Wq_r + (size_t)i * HIDD * HD, Wk_r + (size_t)i * HIDD * HD,
                Wv_r + (size_t)i * HIDD * HD, Ws_r + (size_t)i * HIDD * HIDD,
                bq_r + (size_t)i * HD, bk_r + (size_t)i * HD,
                bv_r + (size_t)i * HD, bs_r + (size_t)i * HIDD, HIDD);
        }
        gemm_tc<<<ggrid, 256>>>(x, l == 0 ? 1 : 0, l == 0 ? IND : HIDD);
        attn_fused<<<NN, 192>>>();
    }

    zero_pool_kernel<<<(NG * HIDD + 255) / 256, 256>>>();
    pool_kernel<<<(NN * HIDD + 255) / 256, 256>>>();
    head_kernel<<<NG, HIDD>>>(fc1w, fc1b, fc2w, fc2b);
    wn_kernel<<<NCLS, HIDD>>>(arcw);
    out_kernel<<<(NG * NCLS + 255) / 256, 256>>>(out);
}

// round 4
// speedup vs baseline: 2.2791x; 1.3136x over previous
#include <cuda_runtime.h>
#include <cuda_bf16.h>
#include <math.h>
#include <stdint.h>

#define NN    20000
#define EE    160000
#define IND   128
#define HIDD  96
#define NH    6
#define NG    512
#define NCLS  128
#define HD    576
#define QC    1824

#define BM 128
#define BN 96
#define BK 32

// ---------------- scratch (allocation-free) ----------------
__device__ float          g_q[(size_t)NN * HD];
__device__ __nv_bfloat16  g_kvh[(size_t)NN * 1152];
__device__ float          g_skip[NN * HIDD];
__device__ float          g_h[NN * HIDD];
__device__ int   g_src[EE], g_dst[EE], g_srcs[EE];
__device__ int   g_deg[NN], g_rowptr[NN + 1], g_cursor[NN];
__device__ int   g_batch[NN];
__device__ float g_pool[NG * HIDD];
__device__ int   g_cnt[NG];
__device__ float g_gbuf[NG * HIDD];
__device__ float g_wn[NCLS * HIDD];
__device__ int   g_is64;

// ---------------- helpers ----------------
__device__ __forceinline__ void mma8(float* c, const unsigned* a, const unsigned* b) {
    asm volatile(
        "mma.sync.aligned.m16n8k8.row.col.f32.tf32.tf32.f32 "
        "{%0,%1,%2,%3}, {%4,%5,%6,%7}, {%8,%9}, {%0,%1,%2,%3};"
        : "+f"(c[0]), "+f"(c[1]), "+f"(c[2]), "+f"(c[3])
        : "r"(a[0]), "r"(a[1]), "r"(a[2]), "r"(a[3]), "r"(b[0]), "r"(b[1]));
}

__device__ __forceinline__ void cpasync16(void* dst, const void* src, bool pred) {
    unsigned sa = (unsigned)__cvta_generic_to_shared(dst);
    int sz = pred ? 16 : 0;
    asm volatile("cp.async.cg.shared.global [%0], [%1], 16, %2;\n"
                 :: "r"(sa), "l"(src), "r"(sz));
}
#define CP_COMMIT() asm volatile("cp.async.commit_group;\n")
#define CP_WAIT(n)  asm volatile("cp.async.wait_group %0;\n" :: "n"(n))

// ---------------- preprocessing ----------------
__global__ void init_kernel(const unsigned* w) {
    int i = blockIdx.x * blockDim.x + threadIdx.x;
    if (i < NN) g_deg[i] = 0;
    if (blockIdx.x == 0) {
        __shared__ int any;
        if (threadIdx.x == 0) any = 0;
        __syncthreads();
        for (int j = threadIdx.x; j < 2048; j += blockDim.x)
            if (w[2 * j + 1] != 0u) any = 1;
        __syncthreads();
        if (threadIdx.x == 0) g_is64 = (any == 0);
    }
}

__global__ void extract_all(const void* ei, const void* bt) {
    int e = blockIdx.x * blockDim.x + threadIdx.x;
    if (e < EE) {
        int s, d;
        if (g_is64) {
            const long long* p = (const long long*)ei;
            s = (int)p[e]; d = (int)p[EE + e];
        } else {
            const int* p = (const int*)ei;
            s = p[e]; d = p[EE + e];
        }
        g_src[e] = s; g_dst[e] = d;
        atomicAdd(&g_deg[d], 1);
    }
    if (e < NN)
        g_batch[e] = g_is64 ? (int)((const long long*)bt)[e] : ((const int*)bt)[e];
}

__global__ void scan_kernel() {
    const int PER = 20;
    int tid = threadIdx.x, lane = tid & 31, wid = tid >> 5;
    int base = tid * PER;
    int sum = 0;
    int lim = (base < NN) ? min(PER, NN - base) : 0;
    if (lim == PER) {
#pragma unroll
        for (int j = 0; j < 5; j++) {
            int4 v = *(const int4*)&g_deg[base + j * 4];
            sum += v.x + v.y + v.z + v.w;
        }
    } else {
        for (int j = 0; j < lim; j++) sum += g_deg[base + j];
    }
    int v = sum;
#pragma unroll
    for (int off = 1; off < 32; off <<= 1) {
        int t = __shfl_up_sync(0xffffffffu, v, off);
        if (lane >= off) v += t;
    }
    __shared__ int wsum[32];
    if (lane == 31) wsum[wid] = v;
    __syncthreads();
    if (wid == 0) {
        int wv = wsum[lane];
#pragma unroll
        for (int off = 1; off < 32; off <<= 1) {
            int t = __shfl_up_sync(0xffffffffu, wv, off);
            if (lane >= off) wv += t;
        }
        wsum[lane] = wv;
    }
    __syncthreads();
    int excl = v - sum + (wid ? wsum[wid - 1] : 0);
    int run = excl;
    for (int j = 0; j < lim; j++) {
        g_rowptr[base + j] = run;
        g_cursor[base + j] = run;
        run += g_deg[base + j];
    }
    if (tid == 1023) g_rowptr[NN] = excl + sum;
}

__global__ void scatter_kernel() {
    int e = blockIdx.x * blockDim.x + threadIdx.x;
    if (e >= EE) return;
    int d = g_dst[e];
    int pos = atomicAdd(&g_cursor[d], 1);
    g_srcs[pos] = g_src[e];
}

// ---------------- TF32 GEMM, cp.async double-buffered, fused weight routing ----------------
__global__ void __launch_bounds__(256) gemm_tc(
        const float* __restrict__ A, int K,
        const float* __restrict__ Wq, const float* __restrict__ Wk,
        const float* __restrict__ Wv, const float* __restrict__ Ws,
        const float* __restrict__ bq, const float* __restrict__ bk,
        const float* __restrict__ bv, const float* __restrict__ bs) {
    __shared__ __align__(16) float As[2][BM][BK + 4];
    __shared__ __align__(16) float Bs[2][BK][BN + 8];
    int tid = threadIdx.x;
    int m0 = blockIdx.y * BM, n0 = blockIdx.x * BN;

    const float* W; const float* bias; int ldw, nbase, segid;
    if (n0 < 576)       { W = Wq; bias = bq; ldw = 576; nbase = n0;        segid = 0; }
    else if (n0 < 1152) { W = Wk; bias = bk; ldw = 576; nbase = n0 - 576;  segid = 1; }
    else if (n0 < 1728) { W = Wv; bias = bv; ldw = 576; nbase = n0 - 1152; segid = 2; }
    else                { W = Ws; bias = bs; ldw = 96;  nbase = 0;         segid = 3; }

    int wid = tid >> 5, lane = tid & 31;
    int wm = wid & 3, wn = wid >> 2;
    int g = lane >> 2, t = lane & 3;
    int c4 = tid & 7, rbase = tid >> 3;
    int bkk = tid / 24, bcc = tid - bkk * 24;

    float acc[2][6][4];
#pragma unroll
    for (int i = 0; i < 2; i++)
#pragma unroll
        for (int j = 0; j < 6; j++)
#pragma unroll
            for (int q = 0; q < 4; q++) acc[i][j][q] = 0.f;

    int KT = K / BK;

#define LOAD_TILES(ST, K0)                                                        \
    do {                                                                          \
        _Pragma("unroll")                                                         \
        for (int i_ = 0; i_ < 4; i_++) {                                          \
            int m_ = rbase + i_ * 32;                                             \
            int gm_ = m0 + m_;                                                    \
            cpasync16(&As[ST][m_][c4 * 4], A + (size_t)gm_ * K + (K0) + c4 * 4,   \
                      gm_ < NN);                                                  \
        }                                                                         \
        _Pragma("unroll")                                                         \
        for (int i_ = 0; i_ < 3; i_++) {                                          \
            int idx_ = tid + i_ * 256;                                            \
            int kk_ = idx_ / 24, cc_ = idx_ - kk_ * 24;                           \
            cpasync16(&Bs[ST][kk_][cc_ * 4],                                      \
                      W + (size_t)((K0) + kk_) * ldw + nbase + cc_ * 4, true);    \
        }                                                                         \
    } while (0)

    LOAD_TILES(0, 0);
    CP_COMMIT();

    for (int kt = 0; kt < KT; kt++) {
        int cur = kt & 1;
        if (kt + 1 < KT) {
            LOAD_TILES(cur ^ 1, (kt + 1) * BK);
            CP_COMMIT();
            CP_WAIT(1);
        } else {
            CP_WAIT(0);
        }
        __syncthreads();
#pragma unroll
        for (int ks = 0; ks < BK; ks += 8) {
            unsigned af[2][4], bf[6][2];
#pragma unroll
            for (int mt = 0; mt < 2; mt++) {
                int mm = wm * 32 + mt * 16 + g;
                af[mt][0] = __float_as_uint(As[cur][mm][ks + t]);
                af[mt][1] = __float_as_uint(As[cur][mm + 8][ks + t]);
                af[mt][2] = __float_as_uint(As[cur][mm][ks + t + 4]);
                af[mt][3] = __float_as_uint(As[cur][mm + 8][ks + t + 4]);
            }
#pragma unroll
            for (int nt = 0; nt < 6; nt++) {
                int nn2 = wn * 48 + nt * 8 + g;
                bf[nt][0] = __float_as_uint(Bs[cur][ks + t][nn2]);
                bf[nt][1] = __float_as_uint(Bs[cur][ks + t + 4][nn2]);
            }
#pragma unroll
            for (int mt = 0; mt < 2; mt++)
#pragma unroll
                for (int nt = 0; nt < 6; nt++)
                    mma8(acc[mt][nt], af[mt], bf[nt]);
        }
        __syncthreads();
    }

#pragma unroll
    for (int mt = 0; mt < 2; mt++) {
        int r0 = m0 + wm * 32 + mt * 16 + g;
#pragma unroll
        for (int nt = 0; nt < 6; nt++) {
            int lc = nbase + wn * 48 + nt * 8 + 2 * t;
            float b0 = bias[lc], b1 = bias[lc + 1];
#pragma unroll
            for (int half = 0; half < 2; half++) {
                int r = r0 + half * 8;
                if (r >= NN) continue;
                float x0 = acc[mt][nt][2 * half] + b0;
                float x1 = acc[mt][nt][2 * half + 1] + b1;
                if (segid == 0) {
                    *(float2*)(g_q + (size_t)r * HD + lc) = make_float2(x0, x1);
                } else if (segid == 3) {
                    *(float2*)(g_skip + (size_t)r * HIDD + lc) = make_float2(x0, x1);
                } else {
                    size_t off = (size_t)r * 1152 + (segid == 2 ? 576 : 0) + lc;
                    *(__nv_bfloat162*)(g_kvh + off) =
                        __float22bfloat162_rn(make_float2(x0, x1));
                }
            }
        }
    }
#undef LOAD_TILES
}

// ---------------- fused attention ----------------
__global__ void __launch_bounds__(192) attn_fused() {
    __shared__ float red[NH][HIDD];
    int n = blockIdx.x;
    int wid = threadIdx.x >> 5, lane = threadIdx.x & 31;
    const float* qr = g_q + (size_t)n * HD + wid * HIDD;
    float q0 = qr[lane], q1 = qr[lane + 32], q2 = qr[lane + 64];
    int beg = g_rowptr[n], end = g_rowptr[n + 1];
    float m = -INFINITY, s = 0.f, a0 = 0.f, a1 = 0.f, a2 = 0.f;
    const float SC = 0.10206207261596577f;
    int i = beg;
    for (; i + 2 <= end; i += 2) {
        int s0 = __ldg(&g_srcs[i]), s1 = __ldg(&g_srcs[i + 1]);
        const __nv_bfloat16* k0r = g_kvh + (size_t)s0 * 1152 + wid * HIDD;
        const __nv_bfloat16* k1r = g_kvh + (size_t)s1 * 1152 + wid * HIDD;
        float p0 = q0 * __bfloat162float(k0r[lane])
                 + q1 * __bfloat162float(k0r[lane + 32])
                 + q2 * __bfloat162float(k0r[lane + 64]);
        float p1 = q0 * __bfloat162float(k1r[lane])
                 + q1 * __bfloat162float(k1r[lane + 32])
                 + q2 * __bfloat162float(k1r[lane + 64]);
#pragma unroll
        for (int off = 16; off > 0; off >>= 1) {
            p0 += __shfl_xor_sync(0xffffffffu, p0, off);
            p1 += __shfl_xor_sync(0xffffffffu, p1, off);
        }
        const __nv_bfloat16* v0r = k0r + 576;
        const __nv_bfloat16* v1r = k1r + 576;
        float v00 = __bfloat162float(v0r[lane]);
        float v01 = __bfloat162float(v0r[lane + 32]);
        float v02 = __bfloat162float(v0r[lane + 64]);
        float v10 = __bfloat162float(v1r[lane]);
        float v11 = __bfloat162float(v1r[lane + 32]);
        float v12 = __bfloat162float(v1r[lane + 64]);
        float al0 = p0 * SC, al1 = p1 * SC;
        float mn = fmaxf(m, fmaxf(al0, al1));
        float corr = __expf(m - mn);
        float w0 = __expf(al0 - mn);
        float w1 = __expf(al1 - mn);
        a0 = a0 * corr + w0 * v00 + w1 * v10;
        a1 = a1 * corr + w0 * v01 + w1 * v11;
        a2 = a2 * corr + w0 * v02 + w1 * v12;
        s = s * corr + w0 + w1;
        m = mn;
    }
    if (i < end) {
        int sv = __ldg(&g_srcs[i]);
        const __nv_bfloat16* kr = g_kvh + (size_t)sv * 1152 + wid * HIDD;
        float p = q0 * __bfloat162float(kr[lane])
                + q1 * __bfloat162float(kr[lane + 32])
                + q2 * __bfloat162float(kr[lane + 64]);
#pragma unroll
        for (int off = 16; off > 0; off >>= 1)
            p += __shfl_xor_sync(0xffffffffu, p, off);
        float al = p * SC;
        float mn = fmaxf(m, al);
        float corr = __expf(m - mn);
        float w = __expf(al - mn);
        const __nv_bfloat16* vr = kr + 576;
        a0 = a0 * corr + w * __bfloat162float(vr[lane]);
        a1 = a1 * corr + w * __bfloat162float(vr[lane + 32]);
        a2 = a2 * corr + w * __bfloat162float(vr[lane + 64]);
        s = s * corr + w;
    }
    float inv = (s > 0.f) ? 1.f / (6.f * s) : 0.f;
    red[wid][lane] = a0 * inv;
    red[wid][lane + 32] = a1 * inv;
    red[wid][lane + 64] = a2 * inv;
    __syncthreads();
    if (threadIdx.x < HIDD) {
        int d = threadIdx.x;
        float v = red[0][d] + red[1][d] + red[2][d] + red[3][d] + red[4][d] + red[5][d];
        v += g_skip[n * HIDD + d];
        g_h[n * HIDD + d] = fmaxf(v, 0.f);
    }
}

// ---------------- pooling + head ----------------
__global__ void zero_pool_kernel() {
    int i = blockIdx.x * blockDim.x + threadIdx.x;
    if (i < NG * HIDD) g_pool[i] = 0.f;
    if (i < NG) g_cnt[i] = 0;
}

__global__ void pool_kernel() {
    int i = blockIdx.x * blockDim.x + threadIdx.x;
    if (i >= NN * HIDD) return;
    int n = i / HIDD, d = i - n * HIDD;
    atomicAdd(&g_pool[g_batch[n] * HIDD + d], g_h[i]);
    if (d == 0) atomicAdd(&g_cnt[g_batch[n]], 1);
}

__global__ void head_kernel(const float* __restrict__ fc1w, const float* __restrict__ fc1b,
                            const float* __restrict__ fc2w, const float* __restrict__ fc2b) {
    int b = blockIdx.x, d = threadIdx.x;
    __shared__ float sg[96], st[96];
    __shared__ float snorm;
    float c = fmaxf((float)g_cnt[b], 1.f);
    sg[d] = g_pool[b * HIDD + d] / c;
    __syncthreads();
    float acc = fc1b[d];
    for (int i = 0; i < HIDD; i++) acc += sg[i] * fc1w[i * HIDD + d];
    st[d] = fmaxf(acc, 0.f);
    __syncthreads();
    acc = fc2b[d];
    for (int i = 0; i < HIDD; i++) acc += st[i] * fc2w[i * HIDD + d];
    float o = fmaxf(acc, 0.f);
    sg[d] = o * o;
    __syncthreads();
    if (d == 0) {
        float ss = 0.f;
        for (int i = 0; i < HIDD; i++) ss += sg[i];
        snorm = sqrtf(ss) + 1e-12f;
    }
    __syncthreads();
    g_gbuf[b * HIDD + d] = o / snorm;
}

__global__ void wn_kernel(const float* __restrict__ arcw) {
    int cIdx = blockIdx.x, d = threadIdx.x;
    __shared__ float sq[96];
    __shared__ float sn;
    float w = arcw[cIdx * HIDD + d];
    sq[d] = w * w;
    __syncthreads();
    if (d == 0) {
        float ss = 0.f;
        for (int i = 0; i < HIDD; i++) ss += sq[i];
        sn = sqrtf(ss) + 1e-12f;
    }
    __syncthreads();
    g_wn[cIdx * HIDD + d] = w / sn;
}

__global__ void out_kernel(float* __restrict__ out) {
    int t = blockIdx.x * blockDim.x + threadIdx.x;
    if (t >= NG * NCLS) return;
    int g = t / NCLS, c = t - g * NCLS;
    float acc = 0.f;
    for (int d = 0; d < HIDD; d++) acc += g_gbuf[g * HIDD + d] * g_wn[c * HIDD + d];
    out[t] = 30.f * acc;
}

// ---------------- driver ----------------
extern "C" void kernel_launch(void* const* d_in, const int* in_sizes, int n_in,
                              void* d_out, int out_size) {
    const float* x    = (const float*)d_in[0];
    const void*  ei   = d_in[1];
    const void*  bt   = d_in[2];
    const float* Wq1  = (const float*)d_in[3];
    const float* bq1  = (const float*)d_in[4];
    const float* Wk1  = (const float*)d_in[5];
    const float* bk1  = (const float*)d_in[6];
    const float* Wv1  = (const float*)d_in[7];
    const float* bv1  = (const float*)d_in[8];
    const float* Ws1  = (const float*)d_in[9];
    const float* bs1  = (const float*)d_in[10];
    const float* Wq_r = (const float*)d_in[11];
    const float* bq_r = (const float*)d_in[12];
    const float* Wk_r = (const float*)d_in[13];
    const float* bk_r = (const float*)d_in[14];
    const float* Wv_r = (const float*)d_in[15];
    const float* bv_r = (const float*)d_in[16];
    const float* Ws_r = (const float*)d_in[17];
    const float* bs_r = (const float*)d_in[18];
    const float* fc1w = (const float*)d_in[19];
    const float* fc1b = (const float*)d_in[20];
    const float* fc2w = (const float*)d_in[21];
    const float* fc2b = (const float*)d_in[22];
    const float* arcw = (const float*)d_in[23];
    float* out = (float*)d_out;

    void* hAddr = nullptr;
    cudaGetSymbolAddress(&hAddr, g_h);     // device-symbol query, no allocation
    const float* hbuf = (const float*)hAddr;

    dim3 ggrid(QC / BN, (NN + BM - 1) / BM);   // 19 x 157

    init_kernel<<<(NN + 255) / 256, 256>>>((const unsigned*)ei);
    extract_all<<<(EE + 255) / 256, 256>>>(ei, bt);
    scan_kernel<<<1, 1024>>>();
    gemm_tc<<<ggrid, 256>>>(x, IND, Wq1, Wk1, Wv1, Ws1, bq1, bk1, bv1, bs1);  // launch #3 -> ncu
    scatter_kernel<<<(EE + 255) / 256, 256>>>();
    attn_fused<<<NN, 192>>>();

    for (int l = 1; l < 5; l++) {
        int i = l - 1;
        gemm_tc<<<ggrid, 256>>>(hbuf, HIDD,
                                Wq_r + (size_t)i * HIDD * HD, Wk_r + (size_t)i * HIDD * HD,
                                Wv_r + (size_t)i * HIDD * HD, Ws_r + (size_t)i * HIDD * HIDD,
                                bq_r + (size_t)i * HD, bk_r + (size_t)i * HD,
                                bv_r + (size_t)i * HD, bs_r + (size_t)i * HIDD);
        attn_fused<<<NN, 192>>>();
    }

    zero_pool_kernel<<<(NG * HIDD + 255) / 256, 256>>>();
    pool_kernel<<<(NN * HIDD + 255) / 256, 256>>>();
    head_kernel<<<NG, HIDD>>>(fc1w, fc1b, fc2w, fc2b);
    wn_kernel<<<NCLS, HIDD>>>(arcw);
    out_kernel<<<(NG * NCLS + 255) / 256, 256>>>(out);
}